// round 10
// baseline (speedup 1.0000x reference)
#include <cuda_runtime.h>
#include <cstdint>

#define N_VARS   2048
#define N_LAYERS 8
#define NODES    4096
#define FAN_IN   4
#define BATCH    8192
#define BT       4              // batch elements per CTA (float4 vector)
#define THREADS  1024
#define NODES_PER_THREAD (NODES / THREADS)   // 4

// Packed per-layer child indices (values < 4096 fit in uint16).
__device__ ushort4 g_idx16[N_LAYERS * NODES];

__global__ void prep_idx_kernel(const int* __restrict__ child_idx) {
    int i = blockIdx.x * blockDim.x + threadIdx.x;
    if (i < N_LAYERS * NODES) {
        const int4 p = reinterpret_cast<const int4*>(child_idx)[i];
        ushort4 v;
        v.x = (unsigned short)(p.x & (NODES - 1));
        v.y = (unsigned short)(p.y & (NODES - 1));
        v.z = (unsigned short)(p.z & (NODES - 1));
        v.w = (unsigned short)(p.w & (NODES - 1));
        g_idx16[i] = v;
    }
}

// All 24 permutations of 4 elements.
__device__ const unsigned char PERM24[24][4] = {
    {0,1,2,3},{0,1,3,2},{0,2,1,3},{0,2,3,1},{0,3,1,2},{0,3,2,1},
    {1,0,2,3},{1,0,3,2},{1,2,0,3},{1,2,3,0},{1,3,0,2},{1,3,2,0},
    {2,0,1,3},{2,0,3,1},{2,1,0,3},{2,1,3,0},{2,3,0,1},{2,3,1,0},
    {3,0,1,2},{3,0,2,1},{3,1,0,2},{3,1,2,0},{3,2,0,1},{3,2,1,0}
};

// Bank-conflict scheduler with iterative refinement.
// prod/sum are commutative -> the order of the 4 child gathers is free.
// LDS.128 conflicts happen within an 8-lane phase (8 consecutive nodes) per
// instruction slot, keyed by bank-group c & 7. Minimize per-slot pileup by
// choosing each node's child->slot permutation; refine with Gauss-Seidel
// sweeps (remove node, re-pick best perm given all others, re-insert).
__global__ void conflict_opt_kernel() {
    int g = blockIdx.x * blockDim.x + threadIdx.x;
    if (g >= N_LAYERS * NODES / 8) return;
    ushort4* base = g_idx16 + (size_t)g * 8;

    unsigned short c[8][4];
    unsigned char  perm[8];
    unsigned char  hist[4][8];

    #pragma unroll
    for (int s = 0; s < 4; s++)
        #pragma unroll
        for (int b = 0; b < 8; b++) hist[s][b] = 0;

    // Initial placement: identity perm.
    for (int n = 0; n < 8; n++) {
        ushort4 v = base[n];
        c[n][0] = v.x; c[n][1] = v.y; c[n][2] = v.z; c[n][3] = v.w;
        perm[n] = 0;
        #pragma unroll
        for (int s = 0; s < 4; s++) hist[s][c[n][s] & 7]++;
    }

    // Refinement sweeps.
    for (int sweep = 0; sweep < 6; sweep++) {
        for (int n = 0; n < 8; n++) {
            // Remove node n's balls.
            const unsigned char* cp = PERM24[perm[n]];
            #pragma unroll
            for (int s = 0; s < 4; s++) hist[s][c[n][cp[s]] & 7]--;

            // Re-pick best permutation given everyone else.
            int best = perm[n];
            int bestCost = 0x7fffffff;
            for (int p = 0; p < 24; p++) {
                const unsigned char* pp = PERM24[p];
                int cost = 0;
                #pragma unroll
                for (int s = 0; s < 4; s++) {
                    int h = hist[s][c[n][pp[s]] & 7];
                    cost += 1 << (2 * h);   // convex pileup penalty
                }
                if (cost < bestCost) { bestCost = cost; best = p; }
            }
            perm[n] = (unsigned char)best;
            const unsigned char* bp = PERM24[best];
            #pragma unroll
            for (int s = 0; s < 4; s++) hist[s][c[n][bp[s]] & 7]++;
        }
    }

    // Write back permuted children.
    for (int n = 0; n < 8; n++) {
        const unsigned char* bp = PERM24[perm[n]];
        ushort4 w;
        w.x = c[n][bp[0]];
        w.y = c[n][bp[1]];
        w.z = c[n][bp[2]];
        w.w = c[n][bp[3]];
        base[n] = w;
    }
}

extern __shared__ float4 s_buf[];   // [2 * NODES] float4 = 128 KB

__global__ __launch_bounds__(THREADS, 1)
void spn_kernel(const float* __restrict__ x,
                const unsigned char* __restrict__ marg,
                float* __restrict__ out) {
    float4* buf0 = s_buf;
    float4* buf1 = s_buf + NODES;

    const int tid = threadIdx.x;
    const int b0  = blockIdx.x * BT;

    // -------- Build leaves: buf0[j] = x[:, j], buf0[j+2048] = 1 - x[:, j] --------
    for (int j = tid; j < N_VARS; j += THREADS) {
        const bool m = (marg[j] != 0);
        float4 v;
        v.x = x[(size_t)(b0 + 0) * N_VARS + j];
        v.y = x[(size_t)(b0 + 1) * N_VARS + j];
        v.z = x[(size_t)(b0 + 2) * N_VARS + j];
        v.w = x[(size_t)(b0 + 3) * N_VARS + j];
        float4 w1, w2;
        if (m) {
            w1 = make_float4(1.f, 1.f, 1.f, 1.f);
            w2 = make_float4(1.f, 1.f, 1.f, 1.f);
        } else {
            w1 = v;
            w2 = make_float4(1.f - v.x, 1.f - v.y, 1.f - v.z, 1.f - v.w);
        }
        buf0[j]          = w1;
        buf0[j + N_VARS] = w2;
    }
    __syncthreads();

    float4* cur = buf0;
    float4* nxt = buf1;
    float4  acc = make_float4(0.f, 0.f, 0.f, 0.f);

    #pragma unroll
    for (int l = 0; l < N_LAYERS; l++) {
        const ushort4* __restrict__ idxL = g_idx16 + l * NODES;

        // Prefetch this thread's index vectors (L2 latency overlapped).
        ushort4 c[NODES_PER_THREAD];
        #pragma unroll
        for (int i = 0; i < NODES_PER_THREAD; i++) {
            c[i] = idxL[tid + i * THREADS];
        }

        #pragma unroll
        for (int i = 0; i < NODES_PER_THREAD; i++) {
            const int node = tid + i * THREADS;
            const float4 a = cur[c[i].x];
            const float4 b = cur[c[i].y];
            const float4 d = cur[c[i].z];
            const float4 e = cur[c[i].w];
            float4 r;
            if ((l & 1) == 0) {   // product layer
                r.x = a.x * b.x * d.x * e.x;
                r.y = a.y * b.y * d.y * e.y;
                r.z = a.z * b.z * d.z * e.z;
                r.w = a.w * b.w * d.w * e.w;
            } else {              // sum layer
                r.x = a.x + b.x + d.x + e.x;
                r.y = a.y + b.y + d.y + e.y;
                r.z = a.z + b.z + d.z + e.z;
                r.w = a.w + b.w + d.w + e.w;
            }
            if (l == N_LAYERS - 1) {
                // Fuse final node-sum: layer 7 is a sum layer, never stored.
                acc.x += r.x; acc.y += r.y; acc.z += r.z; acc.w += r.w;
            } else {
                nxt[node] = r;
            }
        }
        if (l < N_LAYERS - 1) {
            __syncthreads();
        }
        float4* t = cur; cur = nxt; nxt = t;
    }

    // -------- Block reduction of acc (float4) over 1024 threads --------
    #pragma unroll
    for (int off = 16; off > 0; off >>= 1) {
        acc.x += __shfl_down_sync(0xffffffffu, acc.x, off);
        acc.y += __shfl_down_sync(0xffffffffu, acc.y, off);
        acc.z += __shfl_down_sync(0xffffffffu, acc.z, off);
        acc.w += __shfl_down_sync(0xffffffffu, acc.w, off);
    }

    __shared__ float4 warp_sums[THREADS / 32];
    const int wid  = tid >> 5;
    const int lane = tid & 31;
    if (lane == 0) warp_sums[wid] = acc;
    __syncthreads();

    if (wid == 0) {
        float4 s = (lane < THREADS / 32) ? warp_sums[lane]
                                         : make_float4(0.f, 0.f, 0.f, 0.f);
        #pragma unroll
        for (int off = 16; off > 0; off >>= 1) {
            s.x += __shfl_down_sync(0xffffffffu, s.x, off);
            s.y += __shfl_down_sync(0xffffffffu, s.y, off);
            s.z += __shfl_down_sync(0xffffffffu, s.z, off);
            s.w += __shfl_down_sync(0xffffffffu, s.w, off);
        }
        if (lane == 0) {
            *reinterpret_cast<float4*>(out + b0) = s;
        }
    }
}

extern "C" void kernel_launch(void* const* d_in, const int* in_sizes, int n_in,
                              void* d_out, int out_size) {
    const float*         x    = (const float*)d_in[0];
    const unsigned char* marg = (const unsigned char*)d_in[1];
    const int*           cidx = (const int*)d_in[2];   // int64 in reference -> int32 in harness
    float*               out  = (float*)d_out;

    // Allow 128 KB dynamic shared memory (idempotent; not a stream op).
    cudaFuncSetAttribute(spn_kernel,
                         cudaFuncAttributeMaxDynamicSharedMemorySize,
                         2 * NODES * (int)sizeof(float4));

    // 1) Pack int32 indices -> ushort4 (deterministic, re-run every launch).
    {
        const int total = N_LAYERS * NODES;
        const int tpb = 256;
        prep_idx_kernel<<<(total + tpb - 1) / tpb, tpb>>>(cidx);
    }

    // 2) Bank-conflict scheduling with refinement sweeps.
    {
        const int groups = N_LAYERS * NODES / 8;   // 4096
        const int tpb = 256;
        conflict_opt_kernel<<<(groups + tpb - 1) / tpb, tpb>>>();
    }

    // 3) Main fused kernel: one CTA per 4 batch rows.
    spn_kernel<<<BATCH / BT, THREADS, 2 * NODES * (int)sizeof(float4)>>>(x, marg, out);
}

// round 11
// speedup vs baseline: 1.1002x; 1.1002x over previous
#include <cuda_runtime.h>
#include <cstdint>

#define N_VARS   2048
#define N_LAYERS 8
#define NODES    4096
#define FAN_IN   4
#define BATCH    8192
#define BT       4              // batch elements per CTA (float4 vector)
#define THREADS  1024
#define NODES_PER_THREAD (NODES / THREADS)   // 4
#define GROUPS   (N_LAYERS * NODES / 8)      // 4096 8-node phase groups

// Packed per-layer child indices (values < 4096 fit in uint16).
__device__ ushort4 g_idx16[N_LAYERS * NODES];

// All 24 permutations of 4 elements.
__device__ const unsigned char PERM24[24][4] = {
    {0,1,2,3},{0,1,3,2},{0,2,1,3},{0,2,3,1},{0,3,1,2},{0,3,2,1},
    {1,0,2,3},{1,0,3,2},{1,2,0,3},{1,2,3,0},{1,3,0,2},{1,3,2,0},
    {2,0,1,3},{2,0,3,1},{2,1,0,3},{2,1,3,0},{2,3,0,1},{2,3,1,0},
    {3,0,1,2},{3,0,2,1},{3,1,0,2},{3,1,2,0},{3,2,0,1},{3,2,1,0}
};

// Fused prep + greedy bank-conflict scheduler, warp-parallel.
// One warp per 8-node phase group. Greedy sequential over the 8 nodes;
// for each node, lanes 0..23 evaluate one slot-permutation each against the
// current per-slot bank histograms (nibble counters in uint32), warp argmin
// picks the winner (ties -> lowest perm id, matching the serial greedy).
// prod/sum commutativity makes the slot order free; identical schedule to
// the R7 serial greedy, at ~1/100 the serial depth.
__global__ void sched_kernel(const int* __restrict__ cidx) {
    const int gwarp = (blockIdx.x * blockDim.x + threadIdx.x) >> 5;
    const int lane  = threadIdx.x & 31;
    if (gwarp >= GROUPS) return;

    // Lane n (<8) owns node gwarp*8+n: load, mask, pack children + banks.
    unsigned long long my_ch = 0;     // 4 x 16-bit child indices
    unsigned int my_banks = 0;        // 4 x 3-bit bank groups
    if (lane < 8) {
        const int4 p = reinterpret_cast<const int4*>(cidx)[gwarp * 8 + lane];
        const unsigned int c0 = (unsigned int)p.x & (NODES - 1);
        const unsigned int c1 = (unsigned int)p.y & (NODES - 1);
        const unsigned int c2 = (unsigned int)p.z & (NODES - 1);
        const unsigned int c3 = (unsigned int)p.w & (NODES - 1);
        my_ch = (unsigned long long)c0 | ((unsigned long long)c1 << 16)
              | ((unsigned long long)c2 << 32) | ((unsigned long long)c3 << 48);
        my_banks = (c0 & 7) | ((c1 & 7) << 3) | ((c2 & 7) << 6) | ((c3 & 7) << 9);
    }

    // Each of lanes 0..23 caches its permutation row packed into a uint32.
    unsigned int permw = 0;
    if (lane < 24) {
        permw = (unsigned int)PERM24[lane][0]
              | ((unsigned int)PERM24[lane][1] << 8)
              | ((unsigned int)PERM24[lane][2] << 16)
              | ((unsigned int)PERM24[lane][3] << 24);
    }

    // Per-slot bank histograms: 8 banks x 4-bit counters per uint32.
    unsigned int h0 = 0, h1 = 0, h2 = 0, h3 = 0;
    unsigned int my_wperm = 0;        // winning perm for this lane's node

    for (int n = 0; n < 8; n++) {
        const unsigned int bankw = __shfl_sync(0xffffffffu, my_banks, n);

        unsigned int cost = 0x00ffffffu;   // lanes >= 24: +inf (fits <<8)
        if (lane < 24) {
            cost = 0;
            { const int sel = (int)( permw        & 255u); const int b = (bankw >> (sel * 3)) & 7; const int h = (h0 >> (b * 4)) & 15; cost += 1u << (2 * h); }
            { const int sel = (int)((permw >> 8)  & 255u); const int b = (bankw >> (sel * 3)) & 7; const int h = (h1 >> (b * 4)) & 15; cost += 1u << (2 * h); }
            { const int sel = (int)((permw >> 16) & 255u); const int b = (bankw >> (sel * 3)) & 7; const int h = (h2 >> (b * 4)) & 15; cost += 1u << (2 * h); }
            { const int sel = (int)((permw >> 24) & 255u); const int b = (bankw >> (sel * 3)) & 7; const int h = (h3 >> (b * 4)) & 15; cost += 1u << (2 * h); }
        }
        // Warp argmin over (cost, lane) -> lowest cost, tie: lowest perm id.
        unsigned int key = (cost << 8) | (unsigned int)lane;
        #pragma unroll
        for (int off = 16; off > 0; off >>= 1) {
            const unsigned int other = __shfl_xor_sync(0xffffffffu, key, off);
            key = (other < key) ? other : key;
        }
        const int wlane = (int)(key & 255u);
        const unsigned int wperm = __shfl_sync(0xffffffffu, permw, wlane);
        if (lane == n) my_wperm = wperm;

        // All lanes apply the winner's placement to their histogram copies.
        { const int sel = (int)( wperm        & 255u); const int b = (bankw >> (sel * 3)) & 7; h0 += 1u << (b * 4); }
        { const int sel = (int)((wperm >> 8)  & 255u); const int b = (bankw >> (sel * 3)) & 7; h1 += 1u << (b * 4); }
        { const int sel = (int)((wperm >> 16) & 255u); const int b = (bankw >> (sel * 3)) & 7; h2 += 1u << (b * 4); }
        { const int sel = (int)((wperm >> 24) & 255u); const int b = (bankw >> (sel * 3)) & 7; h3 += 1u << (b * 4); }
    }

    // Lane n writes its node's permuted children.
    if (lane < 8) {
        const int s0 = (int)( my_wperm        & 255u);
        const int s1 = (int)((my_wperm >> 8)  & 255u);
        const int s2 = (int)((my_wperm >> 16) & 255u);
        const int s3 = (int)((my_wperm >> 24) & 255u);
        ushort4 w;
        w.x = (unsigned short)((my_ch >> (s0 * 16)) & 0xffffu);
        w.y = (unsigned short)((my_ch >> (s1 * 16)) & 0xffffu);
        w.z = (unsigned short)((my_ch >> (s2 * 16)) & 0xffffu);
        w.w = (unsigned short)((my_ch >> (s3 * 16)) & 0xffffu);
        g_idx16[gwarp * 8 + lane] = w;
    }
}

extern __shared__ float4 s_buf[];   // [2 * NODES] float4 = 128 KB

__global__ __launch_bounds__(THREADS, 1)
void spn_kernel(const float* __restrict__ x,
                const unsigned char* __restrict__ marg,
                float* __restrict__ out) {
    float4* buf0 = s_buf;
    float4* buf1 = s_buf + NODES;

    const int tid = threadIdx.x;
    const int b0  = blockIdx.x * BT;

    // -------- Build leaves: buf0[j] = x[:, j], buf0[j+2048] = 1 - x[:, j] --------
    for (int j = tid; j < N_VARS; j += THREADS) {
        const bool m = (marg[j] != 0);
        float4 v;
        v.x = x[(size_t)(b0 + 0) * N_VARS + j];
        v.y = x[(size_t)(b0 + 1) * N_VARS + j];
        v.z = x[(size_t)(b0 + 2) * N_VARS + j];
        v.w = x[(size_t)(b0 + 3) * N_VARS + j];
        float4 w1, w2;
        if (m) {
            w1 = make_float4(1.f, 1.f, 1.f, 1.f);
            w2 = make_float4(1.f, 1.f, 1.f, 1.f);
        } else {
            w1 = v;
            w2 = make_float4(1.f - v.x, 1.f - v.y, 1.f - v.z, 1.f - v.w);
        }
        buf0[j]          = w1;
        buf0[j + N_VARS] = w2;
    }
    __syncthreads();

    float4* cur = buf0;
    float4* nxt = buf1;
    float4  acc = make_float4(0.f, 0.f, 0.f, 0.f);

    #pragma unroll
    for (int l = 0; l < N_LAYERS; l++) {
        const ushort4* __restrict__ idxL = g_idx16 + l * NODES;

        // Prefetch this thread's index vectors (L2 latency overlapped).
        ushort4 c[NODES_PER_THREAD];
        #pragma unroll
        for (int i = 0; i < NODES_PER_THREAD; i++) {
            c[i] = idxL[tid + i * THREADS];
        }

        #pragma unroll
        for (int i = 0; i < NODES_PER_THREAD; i++) {
            const int node = tid + i * THREADS;
            const float4 a = cur[c[i].x];
            const float4 b = cur[c[i].y];
            const float4 d = cur[c[i].z];
            const float4 e = cur[c[i].w];
            float4 r;
            if ((l & 1) == 0) {   // product layer
                r.x = a.x * b.x * d.x * e.x;
                r.y = a.y * b.y * d.y * e.y;
                r.z = a.z * b.z * d.z * e.z;
                r.w = a.w * b.w * d.w * e.w;
            } else {              // sum layer
                r.x = a.x + b.x + d.x + e.x;
                r.y = a.y + b.y + d.y + e.y;
                r.z = a.z + b.z + d.z + e.z;
                r.w = a.w + b.w + d.w + e.w;
            }
            if (l == N_LAYERS - 1) {
                // Fuse final node-sum: layer 7 is a sum layer, never stored.
                acc.x += r.x; acc.y += r.y; acc.z += r.z; acc.w += r.w;
            } else {
                nxt[node] = r;
            }
        }
        if (l < N_LAYERS - 1) {
            __syncthreads();
        }
        float4* t = cur; cur = nxt; nxt = t;
    }

    // -------- Block reduction of acc (float4) over 1024 threads --------
    #pragma unroll
    for (int off = 16; off > 0; off >>= 1) {
        acc.x += __shfl_down_sync(0xffffffffu, acc.x, off);
        acc.y += __shfl_down_sync(0xffffffffu, acc.y, off);
        acc.z += __shfl_down_sync(0xffffffffu, acc.z, off);
        acc.w += __shfl_down_sync(0xffffffffu, acc.w, off);
    }

    __shared__ float4 warp_sums[THREADS / 32];
    const int wid  = tid >> 5;
    const int lane = tid & 31;
    if (lane == 0) warp_sums[wid] = acc;
    __syncthreads();

    if (wid == 0) {
        float4 s = (lane < THREADS / 32) ? warp_sums[lane]
                                         : make_float4(0.f, 0.f, 0.f, 0.f);
        #pragma unroll
        for (int off = 16; off > 0; off >>= 1) {
            s.x += __shfl_down_sync(0xffffffffu, s.x, off);
            s.y += __shfl_down_sync(0xffffffffu, s.y, off);
            s.z += __shfl_down_sync(0xffffffffu, s.z, off);
            s.w += __shfl_down_sync(0xffffffffu, s.w, off);
        }
        if (lane == 0) {
            *reinterpret_cast<float4*>(out + b0) = s;
        }
    }
}

extern "C" void kernel_launch(void* const* d_in, const int* in_sizes, int n_in,
                              void* d_out, int out_size) {
    const float*         x    = (const float*)d_in[0];
    const unsigned char* marg = (const unsigned char*)d_in[1];
    const int*           cidx = (const int*)d_in[2];   // int64 in reference -> int32 in harness
    float*               out  = (float*)d_out;

    // Allow 128 KB dynamic shared memory (idempotent; host-side, not timed).
    cudaFuncSetAttribute(spn_kernel,
                         cudaFuncAttributeMaxDynamicSharedMemorySize,
                         2 * NODES * (int)sizeof(float4));

    // 1) Fused pack + greedy bank-conflict scheduling (one warp per group).
    {
        const int total_threads = GROUPS * 32;      // 131072
        const int tpb = 256;
        sched_kernel<<<total_threads / tpb, tpb>>>(cidx);
    }

    // 2) Main fused kernel: one CTA per 4 batch rows.
    spn_kernel<<<BATCH / BT, THREADS, 2 * NODES * (int)sizeof(float4)>>>(x, marg, out);
}